// round 17
// baseline (speedup 1.0000x reference)
#include <cuda_runtime.h>
#include <cuda_fp16.h>
#include <math.h>

#define NB   4
#define NL   2048
#define ND   512
#define NH   8
#define NDK  64
#define NM   (NB*NL)   /* 8192 */

// fp16 scratch (static __device__ arrays — allocation-free per harness rules)
__device__ __half g_hx[NM*ND];      // x in fp16
__device__ __half g_hWq[ND*ND];
__device__ __half g_hWk[ND*ND];
__device__ __half g_hWv[ND*ND];
__device__ __half g_hWo[ND*ND];
__device__ __half g_hQ[NM*ND];      // (B,H,L,dk), pre-scaled by 0.125
__device__ __half g_hK[NM*ND];      // (B,H,L,dk)
__device__ __half g_hV[NM*ND];      // (B,H,L,dk)
__device__ __half g_hatt[NM*ND];    // (B,L,D)

// ---------------------------------------------------------------------------
// helpers
// ---------------------------------------------------------------------------
// pack two fp32 into f16x2 (lo = first arg). PTX: first src -> hi half.
__device__ __forceinline__ unsigned packh2(float lo, float hi) {
    unsigned r;
    asm("cvt.rn.f16x2.f32 %0, %1, %2;" : "=r"(r) : "f"(hi), "f"(lo));
    return r;
}
__device__ __forceinline__ unsigned ssa(const void* p) {
    return (unsigned)__cvta_generic_to_shared(p);
}
__device__ __forceinline__ void ldsm4(unsigned* r, unsigned a) {
    asm volatile("ldmatrix.sync.aligned.m8n8.x4.shared.b16 {%0,%1,%2,%3}, [%4];"
                 : "=r"(r[0]), "=r"(r[1]), "=r"(r[2]), "=r"(r[3]) : "r"(a));
}
__device__ __forceinline__ void ldsm4t(unsigned* r, unsigned a) {
    asm volatile("ldmatrix.sync.aligned.m8n8.x4.trans.shared.b16 {%0,%1,%2,%3}, [%4];"
                 : "=r"(r[0]), "=r"(r[1]), "=r"(r[2]), "=r"(r[3]) : "r"(a));
}
__device__ __forceinline__ void ldsm2t(unsigned* r, unsigned a) {
    asm volatile("ldmatrix.sync.aligned.m8n8.x2.trans.shared.b16 {%0,%1}, [%2];"
                 : "=r"(r[0]), "=r"(r[1]) : "r"(a));
}
__device__ __forceinline__ void cpa16(__half* sptr, const __half* gptr) {
    asm volatile("cp.async.cg.shared.global [%0], [%1], 16;"
                 :: "r"(ssa(sptr)), "l"(gptr));
}
__device__ __forceinline__ void cpa_commit() {
    asm volatile("cp.async.commit_group;" ::: "memory");
}
__device__ __forceinline__ void cpa_wait1() {
    asm volatile("cp.async.wait_group 1;" ::: "memory");
}
__device__ __forceinline__ void cpa_wait0() {
    asm volatile("cp.async.wait_group 0;" ::: "memory");
}

// D(16x8) += A(16x16) * B(16x8), fp16 inputs, fp32 accumulate.
__device__ __forceinline__ void mma16(float* d, const unsigned* a, const unsigned* b) {
    asm volatile("mma.sync.aligned.m16n8k16.row.col.f32.f16.f16.f32 "
                 "{%0,%1,%2,%3}, {%4,%5,%6,%7}, {%8,%9}, {%0,%1,%2,%3};"
                 : "+f"(d[0]), "+f"(d[1]), "+f"(d[2]), "+f"(d[3])
                 : "r"(a[0]), "r"(a[1]), "r"(a[2]), "r"(a[3]),
                   "r"(b[0]), "r"(b[1]));
}

// ---------------------------------------------------------------------------
// fp32 -> fp16 conversion: ONE launch covering x + all 4 weights.
// ---------------------------------------------------------------------------
#define CV_X4  (NM * ND / 4)       /* 1048576 */
#define CV_W4  (ND * ND / 4)       /*   65536 */
#define CV_TOT (CV_X4 + 4 * CV_W4) /* 1310720 */

__global__ void to_fp16_all(const float* __restrict__ x,
                            const float* __restrict__ Wq, const float* __restrict__ Wk,
                            const float* __restrict__ Wv, const float* __restrict__ Wo)
{
    int i = blockIdx.x * blockDim.x + threadIdx.x;
    if (i >= CV_TOT) return;
    const float* src;
    __half* dst;
    int off;
    if (i < CV_X4) {
        src = x; dst = g_hx; off = i;
    } else {
        int j = i - CV_X4;
        int seg = j >> 16;          // 65536 float4 per weight
        off = j & 65535;
        src = (seg == 0) ? Wq : (seg == 1) ? Wk : (seg == 2) ? Wv : Wo;
        dst = (seg == 0) ? g_hWq : (seg == 1) ? g_hWk : (seg == 2) ? g_hWv : g_hWo;
    }
    float4 v = ((const float4*)src)[off];
    uint2 o;
    o.x = packh2(v.x, v.y);
    o.y = packh2(v.z, v.w);
    ((uint2*)dst)[off] = o;
}

// ---------------------------------------------------------------------------
// GEMM (fp16 in, ldmatrix fragments, cp.async double-buffered, K-chunk 64):
// Y = X @ W^T. X: (NM,512) fp16, W: (512,512) fp16 ([n][k] row-major).
// Block tile 256m x 64n, 8 warps in 4(m) x 2(n), warp tile 64 x 32.
// Stride 72 halves = 144 B (odd multiple of 16 mod 128 -> ldmatrix
// phase-conflict-free; also 16B-aligned rows for cp.async).
// __launch_bounds__(256,2): reg cap 128 -> 2 blocks/SM.
// mode 0: fp32 Y[m*512+n]; mode 1: fp16 (B,H,L,dk) scatter (h=blockIdx.x),
// with `scale` folded in (0.125 for Q, 1 for K/V).
// ---------------------------------------------------------------------------
#define GST 72
#define MT  4
#define BM  256

__device__ __forceinline__
void gemm_body(const __half* __restrict__ X, const __half* __restrict__ W,
               float* __restrict__ Yf, __half* __restrict__ Yh,
               int mode, float scale)
{
    extern __shared__ __half smh[];
    __half* Xs0 = smh;                       // 2 x BM*GST
    __half* Ws0 = smh + 2 * BM * GST;        // 2 x 64*GST

    const int tid  = threadIdx.x;
    const int w    = tid >> 5, lane = tid & 31;
    const int g    = lane >> 2, t = lane & 3;
    const int wm   = w & 3, wn = w >> 2;
    const int m0   = blockIdx.y * BM, n0 = blockIdx.x * 64;

    float acc[MT][4][4];
    #pragma unroll
    for (int mt = 0; mt < MT; mt++)
        #pragma unroll
        for (int nt = 0; nt < 4; nt++)
            #pragma unroll
            for (int i = 0; i < 4; i++) acc[mt][nt][i] = 0.f;

    // async stage of one K64 chunk into buffer `buf`
    auto stage = [&](int k0, int buf) {
        __half* Xs = Xs0 + buf * BM * GST;
        __half* Ws = Ws0 + buf * 64 * GST;
        #pragma unroll
        for (int i = 0; i < MT * 2; i++) {     // BM rows x 8 chunks / 256 thr
            int idx = tid + 256 * i;
            int r = idx >> 3, c = (idx & 7) * 8;
            cpa16(&Xs[r * GST + c], &X[(size_t)(m0 + r) * 512 + k0 + c]);
        }
        #pragma unroll
        for (int i = 0; i < 2; i++) {          // 64 rows x 8 chunks / 256 thr
            int idx = tid + 256 * i;
            int r = idx >> 3, c = (idx & 7) * 8;
            cpa16(&Ws[r * GST + c], &W[(size_t)(n0 + r) * 512 + k0 + c]);
        }
        cpa_commit();
    };

    const int l15 = lane & 15, lhi = (lane >> 4) & 1;   // A-load lanes
    const int l8  = lane & 7,  seg = lane >> 3;         // B-load lanes

    stage(0, 0);
    for (int kc = 0; kc < 8; kc++) {
        if (kc + 1 < 8) { stage((kc + 1) * 64, (kc + 1) & 1); cpa_wait1(); }
        else            { cpa_wait0(); }
        __syncthreads();

        const __half* Xs = Xs0 + (kc & 1) * BM * GST;
        const __half* Ws = Ws0 + (kc & 1) * 64 * GST;

        #pragma unroll
        for (int ks = 0; ks < 4; ks++) {       // four k16 steps per K64 chunk
            unsigned a[MT][4], bb[4][2];
            #pragma unroll
            for (int mt = 0; mt < MT; mt++) {
                unsigned ad = ssa(&Xs[(wm * (MT * 16) + mt * 16 + l15) * GST
                                      + ks * 16 + lhi * 8]);
                ldsm4(a[mt], ad);
            }
            #pragma unroll
            for (int ntp = 0; ntp < 4; ntp += 2) {
                unsigned bd = ssa(&Ws[(wn * 32 + (ntp + (seg >> 1)) * 8 + l8) * GST
                                      + ks * 16 + (seg & 1) * 8]);
                unsigned r4[4];
                ldsm4(r4, bd);
                bb[ntp][0] = r4[0]; bb[ntp][1] = r4[1];
                bb[ntp + 1][0] = r4[2]; bb[ntp + 1][1] = r4[3];
            }
            #pragma unroll
            for (int mt = 0; mt < MT; mt++)
                #pragma unroll
                for (int nt = 0; nt < 4; nt++)
                    mma16(acc[mt][nt], a[mt], bb[nt]);
        }
        __syncthreads();
    }

    // Epilogue
    #pragma unroll
    for (int mt = 0; mt < MT; mt++) {
        int row = m0 + wm * (MT * 16) + mt * 16 + g;
        #pragma unroll
        for (int nt = 0; nt < 4; nt++) {
            int off = wn * 32 + nt * 8 + 2 * t;      // 0..63 within n-block
            if (mode == 0) {
                float* p = &Yf[(size_t)row * 512 + n0 + off];
                *(float2*)p = make_float2(acc[mt][nt][0], acc[mt][nt][1]);
                *(float2*)(p + (size_t)8 * 512) =
                    make_float2(acc[mt][nt][2], acc[mt][nt][3]);
            } else {
                int b = row >> 11, l = row & 2047, h = blockIdx.x;
                size_t base = ((size_t)((b * 8 + h) * 2048 + l)) * 64 + off;
                *(unsigned*)&Yh[base] =
                    packh2(acc[mt][nt][0] * scale, acc[mt][nt][1] * scale);
                *(unsigned*)&Yh[base + (size_t)8 * 64] =
                    packh2(acc[mt][nt][2] * scale, acc[mt][nt][3] * scale);
            }
        }
    }
}

#define SMEM_GEMM ((2 * BM * GST + 2 * 64 * GST) * 2)   /* 92160 B */

// Fused Q/K/V projection: gridDim.z = 3 selects weight + destination.
__global__ __launch_bounds__(256, 2)
void gemm_qkv()
{
    const __half* W = (blockIdx.z == 0) ? g_hWq : (blockIdx.z == 1) ? g_hWk : g_hWv;
    __half*       Y = (blockIdx.z == 0) ? g_hQ  : (blockIdx.z == 1) ? g_hK  : g_hV;
    float scale = (blockIdx.z == 0) ? 0.125f : 1.f;
    gemm_body(g_hx, W, nullptr, Y, 1, scale);
}

__global__ __launch_bounds__(256, 2)
void gemm_out(float* __restrict__ out)
{
    gemm_body(g_hatt, g_hWo, out, nullptr, 0, 1.f);
}

// ---------------------------------------------------------------------------
// Wave attention (fp16 + ldmatrix): 128 q-rows per block, 4 warps (32 rows
// each as 2 m-tiles), stream 64-key tiles, cp.async double-buffered fp16 K/V.
// FIXED-MAX softmax (scores bounded: p = exp(s), end normalization).
// Row sums via ONES-COLUMN in V: V smem col 64 = 1.0h (cols 65-71 zeroed);
// one extra ldmatrix.x2.trans + 2 mma16 per ks accumulate sum_k p[row,k]
// into Oce — no FADD accumulation, no epilogue reduction (2 broadcasts).
// Smem: Ks[2][64*72] + Vs[2][64*72] halves + wave[2048] f32 = 45056 B.
// ---------------------------------------------------------------------------
#define KS_ST 72
#define SMEM_ATTN (4 * 64 * KS_ST * 2 + 2048 * 4)

__global__ __launch_bounds__(128, 2)
void wave_attn_tc(const float* __restrict__ wfreq, const float* __restrict__ wphase)
{
    extern __shared__ __half smh[];
    __half* Ks0 = smh;
    __half* Vs0 = smh + 2 * 64 * KS_ST;
    float*  Wv  = (float*)(smh + 4 * 64 * KS_ST);

    const int tid = threadIdx.x;
    const int w   = tid >> 5, lane = tid & 31;
    const int g   = lane >> 2, t = lane & 3;
    const int bh  = blockIdx.y, b = bh >> 3, h = bh & 7;
    const int q0  = blockIdx.x * 128;

    const __half* Qh = g_hQ + ((size_t)bh * NL + q0) * NDK;
    const __half* Kh = g_hK + (size_t)bh * NL * NDK;
    const __half* Vh = g_hV + (size_t)bh * NL * NDK;

    // async stage of fp16 K/V tile kt into buffer `buf` (cols 0..63 only)
    auto stage_kv = [&](int kt, int buf) {
        __half* Ksb = Ks0 + buf * 64 * KS_ST;
        __half* Vsb = Vs0 + buf * 64 * KS_ST;
        #pragma unroll
        for (int i = 0; i < 4; i++) {
            int idx = tid + 128 * i;           // 0..511
            int r = idx >> 3, c = (idx & 7) * 8;
            cpa16(&Ksb[r * KS_ST + c], &Kh[(size_t)(kt * 64 + r) * 64 + c]);
            cpa16(&Vsb[r * KS_ST + c], &Vh[(size_t)(kt * 64 + r) * 64 + c]);
        }
        cpa_commit();
    };

    stage_kv(0, 0);   // tile 0 in flight while we do init + Q fragments

    // Ones-column init: V cols 64..71 = {1,0,0,0,0,0,0,0} for both buffers.
    // Staging never touches cols >= 64, so this persists for all tiles.
    {
        int buf = tid >> 6, row = tid & 63;     // 128 threads = 2 x 64 rows
        uint4 ones = make_uint4(0x00003C00u, 0u, 0u, 0u);   // 1.0h, then zeros
        *(uint4*)&Vs0[buf * 64 * KS_ST + row * KS_ST + 64] = ones;
    }

    // Wave table (once per block)
    {
        const float f = wfreq[h], ph = wphase[h];
        const float TWO_PI = 6.28318530717958647692f;
        for (int j = tid; j < NL; j += 128)
            Wv[j] = cosf(TWO_PI * f * (float)j + ph);
    }

    // Q A-fragments straight from gmem (already fp16, pre-scaled)
    unsigned Qa[2][4][4];
    #pragma unroll
    for (int mt = 0; mt < 2; mt++)
        #pragma unroll
        for (int ks = 0; ks < 4; ks++) {
            const __half* qp = &Qh[(w * 32 + mt * 16 + g) * 64 + ks * 16 + 2 * t];
            Qa[mt][ks][0] = *(const unsigned*)&qp[0];
            Qa[mt][ks][1] = *(const unsigned*)&qp[512];
            Qa[mt][ks][2] = *(const unsigned*)&qp[8];
            Qa[mt][ks][3] = *(const unsigned*)&qp[520];
        }

    float Oc[2][8][4];
    #pragma unroll
    for (int mt = 0; mt < 2; mt++)
        #pragma unroll
        for (int nt = 0; nt < 8; nt++)
            #pragma unroll
            for (int i = 0; i < 4; i++) Oc[mt][nt][i] = 0.f;
    float Oce[2][4];                           // ones-column accumulator
    #pragma unroll
    for (int mt = 0; mt < 2; mt++)
        #pragma unroll
        for (int i = 0; i < 4; i++) Oce[mt][i] = 0.f;

    const int l8 = lane & 7, seg = lane >> 3;

    for (int kt = 0; kt < 32; kt++) {
        if (kt + 1 < 32) { stage_kv(kt + 1, (kt + 1) & 1); cpa_wait1(); }
        else             { cpa_wait0(); }
        __syncthreads();

        const __half* Ksb = Ks0 + (kt & 1) * 64 * KS_ST;
        const __half* Vsb = Vs0 + (kt & 1) * 64 * KS_ST;

        // S = Q @ K^T : K fragments via ldmatrix x4 (2 n-tiles per load)
        float Sc[2][8][4];
        #pragma unroll
        for (int mt = 0; mt < 2; mt++)
            #pragma unroll
            for (int nt = 0; nt < 8; nt++)
                #pragma unroll
                for (int i = 0; i < 4; i++) Sc[mt][nt][i] = 0.f;
        #pragma unroll
        for (int ks = 0; ks < 4; ks++) {
            #pragma unroll
            for (int ntp = 0; ntp < 8; ntp += 2) {
                unsigned r4[4];
                unsigned kd = ssa(&Ksb[((ntp + (seg >> 1)) * 8 + l8) * KS_ST
                                       + ks * 16 + (seg & 1) * 8]);
                ldsm4(r4, kd);
                mma16(Sc[0][ntp],     Qa[0][ks], r4);
                mma16(Sc[1][ntp],     Qa[1][ks], r4);
                mma16(Sc[0][ntp + 1], Qa[0][ks], r4 + 2);
                mma16(Sc[1][ntp + 1], Qa[1][ks], r4 + 2);
            }
        }

        // Wave modulation + fixed-max exp (row sums come from the ones-column)
        #pragma unroll
        for (int mt = 0; mt < 2; mt++) {
            #pragma unroll
            for (int nt = 0; nt < 8; nt++) {
                int col = kt * 64 + nt * 8 + 2 * t;
                float w0 = Wv[col], w1 = Wv[col + 1];
                Sc[mt][nt][0] = __expf(Sc[mt][nt][0] * w0);
                Sc[mt][nt][1] = __expf(Sc[mt][nt][1] * w1);
                Sc[mt][nt][2] = __expf(Sc[mt][nt][2] * w0);
                Sc[mt][nt][3] = __expf(Sc[mt][nt][3] * w1);
            }
        }

        // O += P @ V : P A-fragments are packs of the S accumulators;
        // V B-fragments via ldmatrix x4 .trans; ones-tile via ldmatrix x2.
        #pragma unroll
        for (int ks = 0; ks < 4; ks++) {
            unsigned pa[2][4];
            #pragma unroll
            for (int mt = 0; mt < 2; mt++) {
                pa[mt][0] = packh2(Sc[mt][2 * ks][0],     Sc[mt][2 * ks][1]);
                pa[mt][1] = packh2(Sc[mt][2 * ks][2],     Sc[mt][2 * ks][3]);
                pa[mt][2] = packh2(Sc[mt][2 * ks + 1][0], Sc[mt][2 * ks + 1][1]);
                pa[mt][3] = packh2(Sc[mt][2 * ks + 1][2], Sc[mt][2 * ks + 1][3]);
            }
            #pragma unroll
            for (int ntp = 0; ntp < 8; ntp += 2) {
                unsigned r4[4];
                unsigned vd = ssa(&Vsb[(ks * 16 + (seg & 1) * 8 + l8) * KS_ST
                                       + (ntp + (seg >> 1)) * 8]);
                ldsm4t(r4, vd);
                mma16(Oc[0][ntp],     pa[0], r4);
                mma16(Oc[1][ntp],     pa[1], r4);
                mma16(Oc[0][ntp + 1], pa[0], r4 + 2);
                mma16(Oc[1][ntp + 1], pa[1], r4 + 2);
            }
            // ones-column tile (cols 64-71; col 64 = 1.0 -> row sum in n=0)
            {
                unsigned r2[2];
                unsigned od = ssa(&Vsb[(ks * 16 + (seg & 1) * 8 + l8) * KS_ST + 64]);
                ldsm2t(r2, od);
                mma16(Oce[0], pa[0], r2);
                mma16(Oce[1], pa[1], r2);
            }
        }
        __syncthreads();   // before next tile's cp.async overwrites this buffer
    }

    // Epilogue: row sums live in lane 4g (t=0): c0 = rows g, c2 = rows g+8.
    #pragma unroll
    for (int mt = 0; mt < 2; mt++) {
        float sA = __shfl_sync(0xffffffffu, Oce[mt][0], lane & 28);
        float sB = __shfl_sync(0xffffffffu, Oce[mt][2], lane & 28);
        float iA = 1.f / sA, iB = 1.f / sB;

        int rowA = q0 + w * 32 + mt * 16 + g;
        size_t baseA = ((size_t)b * NL + rowA) * ND + h * NDK;
        size_t baseB = baseA + (size_t)8 * ND;
        #pragma unroll
        for (int nt = 0; nt < 8; nt++) {
            int cb = nt * 8 + 2 * t;
            *(unsigned*)&g_hatt[baseA + cb] =
                packh2(Oc[mt][nt][0] * iA, Oc[mt][nt][1] * iA);
            *(unsigned*)&g_hatt[baseB + cb] =
                packh2(Oc[mt][nt][2] * iB, Oc[mt][nt][3] * iB);
        }
    }
}

// ---------------------------------------------------------------------------
extern "C" void kernel_launch(void* const* d_in, const int* in_sizes, int n_in,
                              void* d_out, int out_size)
{
    (void)in_sizes; (void)n_in; (void)out_size;
    const float* x  = (const float*)d_in[0];
    const float* Wq = (const float*)d_in[1];
    const float* Wk = (const float*)d_in[2];
    const float* Wv = (const float*)d_in[3];
    const float* Wo = (const float*)d_in[4];
    const float* wf = (const float*)d_in[5];
    const float* wp = (const float*)d_in[6];
    float* out = (float*)d_out;

    cudaFuncSetAttribute(gemm_qkv, cudaFuncAttributeMaxDynamicSharedMemorySize, SMEM_GEMM);
    cudaFuncSetAttribute(gemm_out, cudaFuncAttributeMaxDynamicSharedMemorySize, SMEM_GEMM);
    cudaFuncSetAttribute(wave_attn_tc, cudaFuncAttributeMaxDynamicSharedMemorySize, SMEM_ATTN);

    // one-time fp32 -> fp16 conversion of all inputs (single launch)
    to_fp16_all<<<(CV_TOT + 255) / 256, 256>>>(x, Wq, Wk, Wv, Wo);

    gemm_qkv<<<dim3(8, 32, 3), 256, SMEM_GEMM>>>();

    wave_attn_tc<<<dim3(16, 32), 128, SMEM_ATTN>>>(wf, wp);

    gemm_out<<<dim3(8, 32), 256, SMEM_GEMM>>>(out);
}